// round 15
// baseline (speedup 1.0000x reference)
#include <cuda_runtime.h>
#include <cstdint>

#define BB 64
#define TT 1024
#define EE 300
#define HH 512
#define G4 2048
#define M_ROWS (BB*TT)

// ---------------- scratch (device globals; no allocations) ----------------
__device__ float    g_out1[(size_t)M_ROWS * EE];   // embeddings
__device__ float    g_zx[(size_t)M_ROWS * G4];     // zx = out1@Wx + b
__device__ uint32_t g_hist[TT + 1][32768];         // h tf32 frag-major, FRESH slab per step
__device__ float    g_c1[BB * 8 * 256];            // conv1 window t=6..13
__device__ float    g_c2[BB * HH];                 // conv2 at t=9
__device__ unsigned g_flags[128 * 32];             // per-CTA barrier flags (128B stride)

// ---------------- tf32 mma.sync helpers ----------------
__device__ __forceinline__ uint32_t f2tf32(float f) {
    uint32_t r; asm("cvt.rna.tf32.f32 %0, %1;" : "=r"(r) : "f"(f)); return r;
}
__device__ __forceinline__ void mma16n8k8(float* d, const uint32_t* a, const uint32_t* b) {
    asm volatile("mma.sync.aligned.m16n8k8.row.col.f32.tf32.tf32.f32 "
        "{%0,%1,%2,%3}, {%4,%5,%6,%7}, {%8,%9}, {%0,%1,%2,%3};"
        : "+f"(d[0]), "+f"(d[1]), "+f"(d[2]), "+f"(d[3])
        : "r"(a[0]), "r"(a[1]), "r"(a[2]), "r"(a[3]), "r"(b[0]), "r"(b[1]));
}

// fragment-layout index for h value (b 0..63, col 0..511)  [proven round-8/9]
__device__ __forceinline__ int htf_idx(int b, int col) {
    int mtv = b >> 4, g2 = b & 7, hi = (b >> 3) & 1;
    int ks = col >> 3, khi = (col >> 2) & 1, kq = col & 3;
    return (((mtv * 64 + ks) << 7) + (g2 << 4) + (kq << 2) + khi * 2 + hi);
}

// ---------------- init: h0 -> g_hist[0], reset flags ----------
__global__ void init_kernel(const float* __restrict__ h0) {
    int i = blockIdx.x * blockDim.x + threadIdx.x;
    if (i < BB * HH) {
        int b = i >> 9, col = i & 511;
        g_hist[0][htf_idx(b, col)] = f2tf32(h0[i]);
    }
    if (i < 128 * 32) g_flags[i] = 0u;
}

// ---------------- embedding gather ----------------
__global__ void embed_kernel(const int* __restrict__ idx, const float* __restrict__ table) {
    long gid = (long)blockIdx.x * blockDim.x + threadIdx.x;
    const long total = (long)M_ROWS * 75;
    if (gid >= total) return;
    long r = gid / 75;
    int  e4 = (int)(gid % 75);
    int row = idx[r];
    ((float4*)g_out1)[r * 75 + e4] = ((const float4*)table)[(long)row * 75 + e4];
}

// ---------------- zx GEMM via mma.sync tf32, register double-buffered -------
#define LDA 136
__global__ __launch_bounds__(256) void zx_gemm_tc(const float* __restrict__ Wx,
                                                  const float* __restrict__ bias) {
    __shared__ uint32_t As[32][LDA];
    __shared__ uint32_t Bs[32][LDA];

    const int tid  = threadIdx.x;
    const int wid  = tid >> 5;
    const int lane = tid & 31;
    const int gid  = lane >> 2;
    const int tig  = lane & 3;
    const int wm   = wid >> 2;
    const int wn   = wid & 3;
    const int bm = blockIdx.y * 128;
    const int bn = blockIdx.x * 128;

    const int arow = tid >> 1;
    const int akh  = (tid & 1) * 16;
    const int bk   = tid >> 3;
    const int bnq  = (tid & 7) * 16;

    float acc[4][4][4];
#pragma unroll
    for (int i = 0; i < 4; i++)
#pragma unroll
        for (int j = 0; j < 4; j++)
#pragma unroll
            for (int c = 0; c < 4; c++) acc[i][j][c] = 0.f;

    float4 aR[4], bR[4];

    // tile loader into registers (boundary-safe: zeros past K=300)
    auto load_tile = [&](int k0) {
        const float* srcA = &g_out1[(size_t)(bm + arow) * EE + k0 + akh];
#pragma unroll
        for (int q = 0; q < 4; q++) {
            int kc = k0 + akh + q * 4;
            float4 v = make_float4(0.f, 0.f, 0.f, 0.f);
            if (kc + 3 < EE) v = *(const float4*)(srcA + q * 4);
            else {
                if (kc + 0 < EE) v.x = srcA[q * 4 + 0];
                if (kc + 1 < EE) v.y = srcA[q * 4 + 1];
                if (kc + 2 < EE) v.z = srcA[q * 4 + 2];
                if (kc + 3 < EE) v.w = srcA[q * 4 + 3];
            }
            aR[q] = v;
        }
#pragma unroll
        for (int q = 0; q < 4; q++) {
            float4 v = make_float4(0.f, 0.f, 0.f, 0.f);
            if (k0 + bk < EE) v = *(const float4*)&Wx[(size_t)(k0 + bk) * G4 + bn + bnq + q * 4];
            bR[q] = v;
        }
    };

    load_tile(0);

    for (int kt = 0; kt < 10; kt++) {
        // store current regs -> smem (with tf32 cvt)
#pragma unroll
        for (int q = 0; q < 4; q++) {
            As[akh + q * 4 + 0][arow] = f2tf32(aR[q].x);
            As[akh + q * 4 + 1][arow] = f2tf32(aR[q].y);
            As[akh + q * 4 + 2][arow] = f2tf32(aR[q].z);
            As[akh + q * 4 + 3][arow] = f2tf32(aR[q].w);
        }
#pragma unroll
        for (int q = 0; q < 4; q++) {
            Bs[bk][bnq + q * 4 + 0] = f2tf32(bR[q].x);
            Bs[bk][bnq + q * 4 + 1] = f2tf32(bR[q].y);
            Bs[bk][bnq + q * 4 + 2] = f2tf32(bR[q].z);
            Bs[bk][bnq + q * 4 + 3] = f2tf32(bR[q].w);
        }
        __syncthreads();

        if (kt < 9) load_tile((kt + 1) * 32);   // LDGs overlap MMAs below

#pragma unroll
        for (int s = 0; s < 4; s++) {
            const int ks = s * 8;
            uint32_t af[4][4], bf[4][2];
#pragma unroll
            for (int mt = 0; mt < 4; mt++) {
                int mb = wm * 64 + mt * 16 + gid;
                af[mt][0] = As[ks + tig][mb];
                af[mt][1] = As[ks + tig][mb + 8];
                af[mt][2] = As[ks + tig + 4][mb];
                af[mt][3] = As[ks + tig + 4][mb + 8];
            }
#pragma unroll
            for (int nt = 0; nt < 4; nt++) {
                int nb = wn * 32 + nt * 8 + gid;
                bf[nt][0] = Bs[ks + tig][nb];
                bf[nt][1] = Bs[ks + tig + 4][nb];
            }
#pragma unroll
            for (int mt = 0; mt < 4; mt++)
#pragma unroll
                for (int nt = 0; nt < 4; nt++)
                    mma16n8k8(acc[mt][nt], af[mt], bf[nt]);
        }
        __syncthreads();
    }

#pragma unroll
    for (int mt = 0; mt < 4; mt++) {
        int r0 = bm + wm * 64 + mt * 16 + gid;
#pragma unroll
        for (int nt = 0; nt < 4; nt++) {
            int ncol = bn + wn * 32 + nt * 8 + tig * 2;
            float2 bv = *(const float2*)&bias[ncol];
            float2 lo = make_float2(acc[mt][nt][0] + bv.x, acc[mt][nt][1] + bv.y);
            float2 hi = make_float2(acc[mt][nt][2] + bv.x, acc[mt][nt][3] + bv.y);
            *(float2*)&g_zx[(size_t)r0 * G4 + ncol] = lo;
            *(float2*)&g_zx[(size_t)(r0 + 8) * G4 + ncol] = hi;
        }
    }
}

// ---------------- conv1: 512 CTAs, one output t per CTA ----------------
__global__ __launch_bounds__(256) void conv1_kernel(const float* __restrict__ W1,
                                                    const float* __restrict__ b1) {
    int bb = blockIdx.x >> 3;
    int th = blockIdx.x & 7;
    __shared__ float xs[10 * EE];
    int tid = threadIdx.x;
    for (int i = tid; i < 10 * EE; i += 256) {
        int rt = i / EE, e = i % EE;
        xs[rt * EE + e] = g_out1[((long)(bb * TT) + 2 + th + rt) * EE + e];
    }
    __syncthreads();
    int m = tid;
    float acc = 0.f;
#pragma unroll 5
    for (int i = 0; i < 10 * EE; i++)
        acc += xs[i] * W1[(size_t)i * 256 + m];
    float v = acc + b1[m];
    v = v > 0.f ? v : 0.f;
    g_c1[(bb * 8 + th) * 256 + m] = v;
}

// ---------------- conv2 at t=9 ----------------
__global__ __launch_bounds__(512) void conv2_kernel(const float* __restrict__ W2,
                                                    const float* __restrict__ b2) {
    int bb = blockIdx.x;
    __shared__ float cs[8 * 256];
    int tid = threadIdx.x;
    for (int i = tid; i < 2048; i += 512) cs[i] = g_c1[bb * 2048 + i];
    __syncthreads();
    int n = tid;
    float acc = 0.f;
#pragma unroll 4
    for (int i = 0; i < 2048; i++)
        acc += cs[i] * W2[(size_t)i * HH + n];
    float v = acc + b2[n];
    v = v > 0.f ? v : 0.f;
    g_c2[bb * HH + n] = v;
}

// ---------------- res9 add ----------------
__global__ void res9_kernel(float* __restrict__ out_res9) {
    int i = blockIdx.x * blockDim.x + threadIdx.x;
    if (i < BB * HH) out_res9[i] += g_c2[i];
}

// ---------------- persistent masked LSTM: 64 CTAs x 512 threads -------------
// Each CTA owns 8 h-cols (32 z-cols). 16 warps = mt(4) x kq(4): warp owns a
// K-quarter of one m16 tile, computes all 4 gate n8-tiles from one A stream
// (zero duplication; 128 KB/CTA/step). Chip L2 broadcast halves to 8 MB/step;
// flag population halves to 64.
#define LC 64

__device__ __forceinline__ float sigf(float x) { return 1.f / (1.f + __expf(-x)); }

__global__ __launch_bounds__(512, 1) void lstm_kernel(const float* __restrict__ Wh,
                                                      const float* __restrict__ c0,
                                                      const float* __restrict__ h0,
                                                      const int* __restrict__ in_seq,
                                                      float* __restrict__ out_enc,
                                                      float* __restrict__ out_res9,
                                                      float* __restrict__ out_c) {
    __shared__ float red[32 * 4 * 66];     // [c(32)][kq(4)][row(66 stride)]  ~33.8 KB
    __shared__ float hstage[512];

    const int tid  = threadIdx.x;
    const int warp = tid >> 5;
    const int lane = tid & 31;
    const int gid  = lane >> 2;
    const int tig  = lane & 3;
    const int mt   = warp >> 2;            // 0..3  batch 16-row tile
    const int kq   = warp & 3;             // 0..3  K-quarter
    const int b    = tid & 63;
    const int jc   = tid >> 6;             // 0..7  local h-col
    const int j0   = blockIdx.x * 8;
    const int col  = j0 + jc;
    const int my_idx = htf_idx(b, col);

    // ---- Wh fragments -> registers: all 4 gate tiles, own K-quarter ----
    uint32_t bfr[4][16][2];
    {
        const int kb = kq * 128;
#pragma unroll
        for (int nt = 0; nt < 4; nt++) {               // nt == gate
            int wcol = j0 + gid + nt * 512;            // h-col = gid
#pragma unroll 16
            for (int ks = 0; ks < 16; ks++) {
                bfr[nt][ks][0] = f2tf32(Wh[(size_t)(kb + ks * 8 + tig) * G4 + wcol]);
                bfr[nt][ks][1] = f2tf32(Wh[(size_t)(kb + ks * 8 + tig + 4) * G4 + wcol]);
            }
        }
    }

    float creg = c0[b * HH + col];
    float hreg = h0[b * HH + col];

    // initial zx/mask prefetch (t=0)
    size_t zb = ((size_t)b * TT) * G4 + col;
    float zr0 = __ldg(&g_zx[zb]);
    float zr1 = __ldg(&g_zx[zb + 512]);
    float zr2 = __ldg(&g_zx[zb + 1024]);
    float zr3 = __ldg(&g_zx[zb + 1536]);
    int   mreg = in_seq[b * TT];
    __syncthreads();

    for (int t = 0; t < TT; t++) {
        // ---- wait for step-t h data (released by all 64 CTAs at t-1) ----
        if (warp == 0 && t > 0) {
            const unsigned tgt = (unsigned)t;
            volatile unsigned* vf = g_flags;
            bool ok;
            do {
                unsigned v0 = vf[lane * 32];
                unsigned v1 = vf[(lane + 32) * 32];
                ok = (v0 >= tgt) && (v1 >= tgt);
            } while (!__all_sync(0xffffffffu, ok));
            asm volatile("fence.acq_rel.gpu;" ::: "memory");
        }
        __syncthreads();

        // ---- MMA: A-frags streamed from global, K-quarter, all 4 gate tiles ----
        float acc[4][4];
#pragma unroll
        for (int nt = 0; nt < 4; nt++)
#pragma unroll
            for (int c = 0; c < 4; c++) acc[nt][c] = 0.f;
        {
            const uint4* hsrc = (const uint4*)(g_hist[t] + mt * 8192 + kq * 2048) + lane;
            uint4 ab[8];
#pragma unroll
            for (int p = 0; p < 8; p++) ab[p] = __ldg(hsrc + p * 32);
#pragma unroll 16
            for (int ks = 0; ks < 16; ks++) {
                uint32_t af[4];
                *(uint4*)af = ab[ks & 7];
                if (ks < 8) ab[ks & 7] = __ldg(hsrc + (ks + 8) * 32);
                mma16n8k8(acc[0], af, bfr[0][ks]);
                mma16n8k8(acc[1], af, bfr[1][ks]);
                mma16n8k8(acc[2], af, bfr[2][ks]);
                mma16n8k8(acc[3], af, bfr[3][ks]);
            }
        }

        // ---- funnel partials -> red[c][kq][row] ----
        {
            int r0 = mt * 16 + gid;
#pragma unroll
            for (int nt = 0; nt < 4; nt++) {
                int c0i = nt * 8 + tig * 2;
                red[((c0i    ) * 4 + kq) * 66 + r0]     = acc[nt][0];
                red[((c0i + 1) * 4 + kq) * 66 + r0]     = acc[nt][1];
                red[((c0i    ) * 4 + kq) * 66 + r0 + 8] = acc[nt][2];
                red[((c0i + 1) * 4 + kq) * 66 + r0 + 8] = acc[nt][3];
            }
        }
        __syncthreads();

        // ---- gates: one (b, col) per thread (all 512); sum kq partials ----
        {
            float z0 = zr0, z1 = zr1, z2 = zr2, z3 = zr3;
#pragma unroll
            for (int q = 0; q < 4; q++) {
                z0 += red[((0 * 8 + jc) * 4 + q) * 66 + b];
                z1 += red[((1 * 8 + jc) * 4 + q) * 66 + b];
                z2 += red[((2 * 8 + jc) * 4 + q) * 66 + b];
                z3 += red[((3 * 8 + jc) * 4 + q) * 66 + b];
            }
            float cn = sigf(z1) * creg + sigf(z0) * tanhf(z2);
            float hn = sigf(z3) * tanhf(cn);
            if (mreg == 0) { hn = hreg; cn = creg; }    // masked: carry state
            creg = cn; hreg = hn;
            hstage[b * 8 + jc] = hn;
            __stcg(&g_hist[t + 1][my_idx], f2tf32(hn));
            if (t == 9)      out_res9[b * HH + col] = hn;
            if (t == TT - 1) out_c[b * HH + col] = cn;
        }
        __syncthreads();

        // ---- release flag EARLY (h stores are ordered by release) ----
        if (tid == 0) {
            unsigned v = (unsigned)(t + 1);
            asm volatile("st.release.gpu.global.u32 [%0], %1;"
                         :: "l"(&g_flags[blockIdx.x * 32]), "r"(v) : "memory");
        }

        // ---- out_enc store + next-step zx prefetch (overlaps peers' polls) ----
        if (tid < 128) {
            int row = tid >> 1, half = tid & 1;
            float4 hv4 = *(const float4*)&hstage[row * 8 + half * 4];
            *(float4*)&out_enc[((size_t)row * TT + t) * HH + j0 + half * 4] = hv4;
        }
        if (t + 1 < TT) {
            zb = ((size_t)b * TT + (t + 1)) * G4 + col;
            zr0 = __ldg(&g_zx[zb]);
            zr1 = __ldg(&g_zx[zb + 512]);
            zr2 = __ldg(&g_zx[zb + 1024]);
            zr3 = __ldg(&g_zx[zb + 1536]);
            mreg = in_seq[b * TT + t + 1];
        }
    }
}

// ---------------- launch ----------------
extern "C" void kernel_launch(void* const* d_in, const int* in_sizes, int n_in,
                              void* d_out, int out_size) {
    const int*   in_seq = (const int*)  d_in[0];
    const float* h0     = (const float*)d_in[1];
    const float* c0     = (const float*)d_in[2];
    const float* table  = (const float*)d_in[3];
    const float* W1     = (const float*)d_in[4];
    const float* b1     = (const float*)d_in[5];
    const float* W2     = (const float*)d_in[6];
    const float* b2     = (const float*)d_in[7];
    const float* Wx     = (const float*)d_in[8];
    const float* Wh     = (const float*)d_in[9];
    const float* bias   = (const float*)d_in[10];

    float* out      = (float*)d_out;
    float* out_enc  = out;
    float* out_res9 = out + (size_t)BB * TT * HH;
    float* out_c    = out_res9 + BB * HH;

    init_kernel<<<(BB * HH + 255) / 256, 256>>>(h0);
    embed_kernel<<<(int)(((long)M_ROWS * 75 + 255) / 256), 256>>>(in_seq, table);
    dim3 gg(G4 / 128, M_ROWS / 128);
    zx_gemm_tc<<<gg, 256>>>(Wx, bias);
    lstm_kernel<<<LC, 512>>>(Wh, c0, h0, in_seq, out_enc, out_res9, out_c);  // #4 -> profiled
    conv1_kernel<<<BB * 8, 256>>>(W1, b1);
    conv2_kernel<<<BB, 512>>>(W2, b2);
    res9_kernel<<<(BB * HH + 255) / 256, 256>>>(out_res9);
}

// round 17
// speedup vs baseline: 1.4406x; 1.4406x over previous
#include <cuda_runtime.h>
#include <cstdint>

#define BB 64
#define TT 1024
#define EE 300
#define HH 512
#define G4 2048
#define M_ROWS (BB*TT)

// ---------------- scratch (device globals; no allocations) ----------------
__device__ float    g_out1[(size_t)M_ROWS * EE];   // embeddings
__device__ float    g_zx[(size_t)M_ROWS * G4];     // zx = out1@Wx + b
__device__ uint32_t g_hist[TT + 1][32768];         // h tf32 frag-major, FRESH slab per step
__device__ float    g_c1[BB * 8 * 256];            // conv1 window t=6..13
__device__ float    g_c2[BB * HH];                 // conv2 at t=9
__device__ unsigned g_flags[128 * 32];             // per-CTA barrier flags (128B stride)

// ---------------- tf32 mma.sync helpers ----------------
__device__ __forceinline__ uint32_t f2tf32(float f) {
    uint32_t r; asm("cvt.rna.tf32.f32 %0, %1;" : "=r"(r) : "f"(f)); return r;
}
__device__ __forceinline__ void mma16n8k8(float* d, const uint32_t* a, const uint32_t* b) {
    asm volatile("mma.sync.aligned.m16n8k8.row.col.f32.tf32.tf32.f32 "
        "{%0,%1,%2,%3}, {%4,%5,%6,%7}, {%8,%9}, {%0,%1,%2,%3};"
        : "+f"(d[0]), "+f"(d[1]), "+f"(d[2]), "+f"(d[3])
        : "r"(a[0]), "r"(a[1]), "r"(a[2]), "r"(a[3]), "r"(b[0]), "r"(b[1]));
}

// fragment-layout index for h value (b 0..63, col 0..511)  [proven round-8/9]
__device__ __forceinline__ int htf_idx(int b, int col) {
    int mtv = b >> 4, g2 = b & 7, hi = (b >> 3) & 1;
    int ks = col >> 3, khi = (col >> 2) & 1, kq = col & 3;
    return (((mtv * 64 + ks) << 7) + (g2 << 4) + (kq << 2) + khi * 2 + hi);
}

// ---------------- init: h0 -> g_hist[0], reset flags ----------
__global__ void init_kernel(const float* __restrict__ h0) {
    int i = blockIdx.x * blockDim.x + threadIdx.x;
    if (i < BB * HH) {
        int b = i >> 9, col = i & 511;
        g_hist[0][htf_idx(b, col)] = f2tf32(h0[i]);
    }
    if (i < 128 * 32) g_flags[i] = 0u;
}

// ---------------- embedding gather ----------------
__global__ void embed_kernel(const int* __restrict__ idx, const float* __restrict__ table) {
    long gid = (long)blockIdx.x * blockDim.x + threadIdx.x;
    const long total = (long)M_ROWS * 75;
    if (gid >= total) return;
    long r = gid / 75;
    int  e4 = (int)(gid % 75);
    int row = idx[r];
    ((float4*)g_out1)[r * 75 + e4] = ((const float4*)table)[(long)row * 75 + e4];
}

// ---------------- zx GEMM via mma.sync tf32, register double-buffered -------
#define LDA 136
__global__ __launch_bounds__(256) void zx_gemm_tc(const float* __restrict__ Wx,
                                                  const float* __restrict__ bias) {
    __shared__ uint32_t As[32][LDA];
    __shared__ uint32_t Bs[32][LDA];

    const int tid  = threadIdx.x;
    const int wid  = tid >> 5;
    const int lane = tid & 31;
    const int gid  = lane >> 2;
    const int tig  = lane & 3;
    const int wm   = wid >> 2;
    const int wn   = wid & 3;
    const int bm = blockIdx.y * 128;
    const int bn = blockIdx.x * 128;

    const int arow = tid >> 1;
    const int akh  = (tid & 1) * 16;
    const int bk   = tid >> 3;
    const int bnq  = (tid & 7) * 16;

    float acc[4][4][4];
#pragma unroll
    for (int i = 0; i < 4; i++)
#pragma unroll
        for (int j = 0; j < 4; j++)
#pragma unroll
            for (int c = 0; c < 4; c++) acc[i][j][c] = 0.f;

    float4 aR[4], bR[4];

    auto load_tile = [&](int k0) {
        const float* srcA = &g_out1[(size_t)(bm + arow) * EE + k0 + akh];
#pragma unroll
        for (int q = 0; q < 4; q++) {
            int kc = k0 + akh + q * 4;
            float4 v = make_float4(0.f, 0.f, 0.f, 0.f);
            if (kc + 3 < EE) v = *(const float4*)(srcA + q * 4);
            else {
                if (kc + 0 < EE) v.x = srcA[q * 4 + 0];
                if (kc + 1 < EE) v.y = srcA[q * 4 + 1];
                if (kc + 2 < EE) v.z = srcA[q * 4 + 2];
                if (kc + 3 < EE) v.w = srcA[q * 4 + 3];
            }
            aR[q] = v;
        }
#pragma unroll
        for (int q = 0; q < 4; q++) {
            float4 v = make_float4(0.f, 0.f, 0.f, 0.f);
            if (k0 + bk < EE) v = *(const float4*)&Wx[(size_t)(k0 + bk) * G4 + bn + bnq + q * 4];
            bR[q] = v;
        }
    };

    load_tile(0);

    for (int kt = 0; kt < 10; kt++) {
#pragma unroll
        for (int q = 0; q < 4; q++) {
            As[akh + q * 4 + 0][arow] = f2tf32(aR[q].x);
            As[akh + q * 4 + 1][arow] = f2tf32(aR[q].y);
            As[akh + q * 4 + 2][arow] = f2tf32(aR[q].z);
            As[akh + q * 4 + 3][arow] = f2tf32(aR[q].w);
        }
#pragma unroll
        for (int q = 0; q < 4; q++) {
            Bs[bk][bnq + q * 4 + 0] = f2tf32(bR[q].x);
            Bs[bk][bnq + q * 4 + 1] = f2tf32(bR[q].y);
            Bs[bk][bnq + q * 4 + 2] = f2tf32(bR[q].z);
            Bs[bk][bnq + q * 4 + 3] = f2tf32(bR[q].w);
        }
        __syncthreads();

        if (kt < 9) load_tile((kt + 1) * 32);   // LDGs overlap MMAs below

#pragma unroll
        for (int s = 0; s < 4; s++) {
            const int ks = s * 8;
            uint32_t af[4][4], bf[4][2];
#pragma unroll
            for (int mt = 0; mt < 4; mt++) {
                int mb = wm * 64 + mt * 16 + gid;
                af[mt][0] = As[ks + tig][mb];
                af[mt][1] = As[ks + tig][mb + 8];
                af[mt][2] = As[ks + tig + 4][mb];
                af[mt][3] = As[ks + tig + 4][mb + 8];
            }
#pragma unroll
            for (int nt = 0; nt < 4; nt++) {
                int nb = wn * 32 + nt * 8 + gid;
                bf[nt][0] = Bs[ks + tig][nb];
                bf[nt][1] = Bs[ks + tig + 4][nb];
            }
#pragma unroll
            for (int mt = 0; mt < 4; mt++)
#pragma unroll
                for (int nt = 0; nt < 4; nt++)
                    mma16n8k8(acc[mt][nt], af[mt], bf[nt]);
        }
        __syncthreads();
    }

#pragma unroll
    for (int mt = 0; mt < 4; mt++) {
        int r0 = bm + wm * 64 + mt * 16 + gid;
#pragma unroll
        for (int nt = 0; nt < 4; nt++) {
            int ncol = bn + wn * 32 + nt * 8 + tig * 2;
            float2 bv = *(const float2*)&bias[ncol];
            float2 lo = make_float2(acc[mt][nt][0] + bv.x, acc[mt][nt][1] + bv.y);
            float2 hi = make_float2(acc[mt][nt][2] + bv.x, acc[mt][nt][3] + bv.y);
            *(float2*)&g_zx[(size_t)r0 * G4 + ncol] = lo;
            *(float2*)&g_zx[(size_t)(r0 + 8) * G4 + ncol] = hi;
        }
    }
}

// ---------------- conv1: 512 CTAs, one output t per CTA ----------------
__global__ __launch_bounds__(256) void conv1_kernel(const float* __restrict__ W1,
                                                    const float* __restrict__ b1) {
    int bb = blockIdx.x >> 3;
    int th = blockIdx.x & 7;
    __shared__ float xs[10 * EE];
    int tid = threadIdx.x;
    for (int i = tid; i < 10 * EE; i += 256) {
        int rt = i / EE, e = i % EE;
        xs[rt * EE + e] = g_out1[((long)(bb * TT) + 2 + th + rt) * EE + e];
    }
    __syncthreads();
    int m = tid;
    float acc = 0.f;
#pragma unroll 5
    for (int i = 0; i < 10 * EE; i++)
        acc += xs[i] * W1[(size_t)i * 256 + m];
    float v = acc + b1[m];
    v = v > 0.f ? v : 0.f;
    g_c1[(bb * 8 + th) * 256 + m] = v;
}

// ---------------- conv2 at t=9 ----------------
__global__ __launch_bounds__(512) void conv2_kernel(const float* __restrict__ W2,
                                                    const float* __restrict__ b2) {
    int bb = blockIdx.x;
    __shared__ float cs[8 * 256];
    int tid = threadIdx.x;
    for (int i = tid; i < 2048; i += 512) cs[i] = g_c1[bb * 2048 + i];
    __syncthreads();
    int n = tid;
    float acc = 0.f;
#pragma unroll 4
    for (int i = 0; i < 2048; i++)
        acc += cs[i] * W2[(size_t)i * HH + n];
    float v = acc + b2[n];
    v = v > 0.f ? v : 0.f;
    g_c2[bb * HH + n] = v;
}

// ---------------- res9 add ----------------
__global__ void res9_kernel(float* __restrict__ out_res9) {
    int i = blockIdx.x * blockDim.x + threadIdx.x;
    if (i < BB * HH) out_res9[i] += g_c2[i];
}

// ---------------- persistent masked LSTM: round-13 proven config ------------
// 128 CTAs x 256 thr; 8 warps = mt(4) x kh(2): each warp owns m16 rows and a
// K-half, computes BOTH n8 tiles from one A stream (128 KB/CTA/step floor).
#define LC 128

__device__ __forceinline__ float sigf(float x) { return 1.f / (1.f + __expf(-x)); }

__global__ __launch_bounds__(256, 1) void lstm_kernel(const float* __restrict__ Wh,
                                                      const float* __restrict__ c0,
                                                      const float* __restrict__ h0,
                                                      const int* __restrict__ in_seq,
                                                      float* __restrict__ out_enc,
                                                      float* __restrict__ out_res9,
                                                      float* __restrict__ out_c) {
    __shared__ float red[16 * 2 * 66];     // [col(16)][kh(2)][row(66 stride)]
    __shared__ float hstage[256];

    const int tid  = threadIdx.x;
    const int warp = tid >> 5;
    const int lane = tid & 31;
    const int gid  = lane >> 2;
    const int tig  = lane & 3;
    const int mt   = warp >> 1;            // 0..3  batch 16-row tile
    const int kh   = warp & 1;             // 0..1  K-half
    const int b    = tid & 63;
    const int jc   = tid >> 6;
    const int j0   = blockIdx.x * 4;
    const int col  = j0 + jc;
    const int my_idx = htf_idx(b, col);

    // ---- Wh fragments -> registers: both n8 tiles, own K-half ----
    uint32_t bfr[2][32][2];
    {
        const int kb = kh * 256;
#pragma unroll
        for (int nt = 0; nt < 2; nt++) {
            int c  = nt * 8 + gid;
            int g  = c >> 2, jj = c & 3;
            int wcol = j0 + jj + g * 512;
#pragma unroll 32
            for (int ks = 0; ks < 32; ks++) {
                bfr[nt][ks][0] = f2tf32(Wh[(size_t)(kb + ks * 8 + tig) * G4 + wcol]);
                bfr[nt][ks][1] = f2tf32(Wh[(size_t)(kb + ks * 8 + tig + 4) * G4 + wcol]);
            }
        }
    }

    float creg = c0[b * HH + col];
    float hreg = h0[b * HH + col];

    // initial zx/mask prefetch (t=0)
    size_t zb = ((size_t)b * TT) * G4 + col;
    float zr0 = __ldg(&g_zx[zb]);
    float zr1 = __ldg(&g_zx[zb + 512]);
    float zr2 = __ldg(&g_zx[zb + 1024]);
    float zr3 = __ldg(&g_zx[zb + 1536]);
    int   mreg = in_seq[b * TT];
    __syncthreads();

    for (int t = 0; t < TT; t++) {
        // ---- wait for step-t h data (release by all CTAs at t-1) ----
        if (warp == 0 && t > 0) {
            const unsigned tgt = (unsigned)t;
            volatile unsigned* vf = g_flags;
            bool ok;
            do {
                unsigned v0 = vf[lane * 32];
                unsigned v1 = vf[(lane + 32) * 32];
                unsigned v2 = vf[(lane + 64) * 32];
                unsigned v3 = vf[(lane + 96) * 32];
                ok = (v0 >= tgt) && (v1 >= tgt) && (v2 >= tgt) && (v3 >= tgt);
            } while (!__all_sync(0xffffffffu, ok));
            asm volatile("fence.acq_rel.gpu;" ::: "memory");
        }
        __syncthreads();

        // ---- MMA: A-frags streamed from global, one K-half, both n-tiles ----
        float acc0[4] = {0.f, 0.f, 0.f, 0.f};
        float acc1[4] = {0.f, 0.f, 0.f, 0.f};
        {
            const uint4* hsrc = (const uint4*)(g_hist[t] + mt * 8192 + kh * 4096) + lane;
            uint4 ab[8];
#pragma unroll
            for (int p = 0; p < 8; p++) ab[p] = __ldg(hsrc + p * 32);
#pragma unroll 32
            for (int ks = 0; ks < 32; ks++) {
                uint32_t af[4];
                *(uint4*)af = ab[ks & 7];
                if (ks < 24) ab[ks & 7] = __ldg(hsrc + (ks + 8) * 32);
                mma16n8k8(acc0, af, bfr[0][ks]);
                mma16n8k8(acc1, af, bfr[1][ks]);
            }
        }

        // ---- funnel partials -> red[col][kh][row] ----
        {
            int r0 = mt * 16 + gid;
#pragma unroll
            for (int nt = 0; nt < 2; nt++) {
                const float* a = nt ? acc1 : acc0;
                int c0i = nt * 8 + tig * 2;
                red[((c0i    ) * 2 + kh) * 66 + r0]     = a[0];
                red[((c0i + 1) * 2 + kh) * 66 + r0]     = a[1];
                red[((c0i    ) * 2 + kh) * 66 + r0 + 8] = a[2];
                red[((c0i + 1) * 2 + kh) * 66 + r0 + 8] = a[3];
            }
        }
        __syncthreads();

        // ---- gates: one (b, col) per thread; sum kh partials ----
        {
            float z0 = zr0 + red[((0 * 4 + jc) * 2) * 66 + b] + red[((0 * 4 + jc) * 2 + 1) * 66 + b];
            float z1 = zr1 + red[((1 * 4 + jc) * 2) * 66 + b] + red[((1 * 4 + jc) * 2 + 1) * 66 + b];
            float z2 = zr2 + red[((2 * 4 + jc) * 2) * 66 + b] + red[((2 * 4 + jc) * 2 + 1) * 66 + b];
            float z3 = zr3 + red[((3 * 4 + jc) * 2) * 66 + b] + red[((3 * 4 + jc) * 2 + 1) * 66 + b];
            float cn = sigf(z1) * creg + sigf(z0) * tanhf(z2);
            float hn = sigf(z3) * tanhf(cn);
            if (mreg == 0) { hn = hreg; cn = creg; }    // masked: carry state
            creg = cn; hreg = hn;
            hstage[b * 4 + jc] = hn;
            __stcg(&g_hist[t + 1][my_idx], f2tf32(hn));
            if (t == 9)      out_res9[b * HH + col] = hn;
            if (t == TT - 1) out_c[b * HH + col] = cn;
        }
        __syncthreads();

        // ---- release flag EARLY (h stores are ordered by release) ----
        if (tid == 0) {
            unsigned v = (unsigned)(t + 1);
            asm volatile("st.release.gpu.global.u32 [%0], %1;"
                         :: "l"(&g_flags[blockIdx.x * 32]), "r"(v) : "memory");
        }

        // ---- out_enc store + next-step zx prefetch (overlaps peers' polls) ----
        if (tid < 64) {
            float4 hv4 = *(const float4*)&hstage[tid * 4];
            *(float4*)&out_enc[((size_t)tid * TT + t) * HH + j0] = hv4;
        }
        if (t + 1 < TT) {
            zb = ((size_t)b * TT + (t + 1)) * G4 + col;
            zr0 = __ldg(&g_zx[zb]);
            zr1 = __ldg(&g_zx[zb + 512]);
            zr2 = __ldg(&g_zx[zb + 1024]);
            zr3 = __ldg(&g_zx[zb + 1536]);
            mreg = in_seq[b * TT + t + 1];
        }
    }
}

// ---------------- launch ----------------
extern "C" void kernel_launch(void* const* d_in, const int* in_sizes, int n_in,
                              void* d_out, int out_size) {
    const int*   in_seq = (const int*)  d_in[0];
    const float* h0     = (const float*)d_in[1];
    const float* c0     = (const float*)d_in[2];
    const float* table  = (const float*)d_in[3];
    const float* W1     = (const float*)d_in[4];
    const float* b1     = (const float*)d_in[5];
    const float* W2     = (const float*)d_in[6];
    const float* b2     = (const float*)d_in[7];
    const float* Wx     = (const float*)d_in[8];
    const float* Wh     = (const float*)d_in[9];
    const float* bias   = (const float*)d_in[10];

    float* out      = (float*)d_out;
    float* out_enc  = out;
    float* out_res9 = out + (size_t)BB * TT * HH;
    float* out_c    = out_res9 + BB * HH;

    init_kernel<<<(BB * HH + 255) / 256, 256>>>(h0);
    embed_kernel<<<(int)(((long)M_ROWS * 75 + 255) / 256), 256>>>(in_seq, table);
    dim3 gg(G4 / 128, M_ROWS / 128);
    zx_gemm_tc<<<gg, 256>>>(Wx, bias);
    lstm_kernel<<<LC, 256>>>(Wh, c0, h0, in_seq, out_enc, out_res9, out_c);  // #4 -> profiled
    conv1_kernel<<<BB * 8, 256>>>(W1, b1);
    conv2_kernel<<<BB, 512>>>(W2, b2);
    res9_kernel<<<(BB * HH + 255) / 256, 256>>>(out_res9);
}